// round 16
// baseline (speedup 1.0000x reference)
#include <cuda_runtime.h>
#include <cuda_fp16.h>
#include <cstdint>

#define N_NODES 100000
#define N_EDGES 1600000
#define IN_F    512
#define OUT_F   256

// Scratch (no cudaMalloc). H and T are fp16 (range-safe: |H|<=1, |T|<~16).
__device__ __half g_H[(size_t)N_NODES * OUT_F];
__device__ __half g_T[(size_t)N_NODES * OUT_F];
__device__ int    g_row_ptr[N_NODES + 1];
// fp16 weight [512][256], 256 KB — L2-resident.
__device__ __half g_Wh[(size_t)IN_F * OUT_F];

// ---------------------------------------------------------------------------
// helpers
// ---------------------------------------------------------------------------
__device__ __forceinline__ uint32_t smem_u32(const void* p) {
    uint32_t a;
    asm("{ .reg .u64 t; cvta.to.shared.u64 t, %1; cvt.u32.u64 %0, t; }" : "=r"(a) : "l"(p));
    return a;
}
__device__ __forceinline__ float tanh_fast(float x) {
    float y;
    asm("tanh.approx.f32 %0, %1;" : "=f"(y) : "f"(x));
    return y;
}
__device__ __forceinline__ void ldsm_x4(uint32_t* r, uint32_t addr) {
    asm volatile("ldmatrix.sync.aligned.m8n8.x4.shared.b16 {%0,%1,%2,%3}, [%4];"
                 : "=r"(r[0]), "=r"(r[1]), "=r"(r[2]), "=r"(r[3]) : "r"(addr));
}
__device__ __forceinline__ void ldsm_x4_t(uint32_t* r, uint32_t addr) {
    asm volatile("ldmatrix.sync.aligned.m8n8.x4.trans.shared.b16 {%0,%1,%2,%3}, [%4];"
                 : "=r"(r[0]), "=r"(r[1]), "=r"(r[2]), "=r"(r[3]) : "r"(addr));
}
__device__ __forceinline__ void mma_f16(float* c, const uint32_t* a, const uint32_t* b) {
    asm volatile(
        "mma.sync.aligned.m16n8k16.row.col.f32.f16.f16.f32 "
        "{%0,%1,%2,%3}, {%4,%5,%6,%7}, {%8,%9}, {%0,%1,%2,%3};"
        : "+f"(c[0]), "+f"(c[1]), "+f"(c[2]), "+f"(c[3])
        : "r"(a[0]), "r"(a[1]), "r"(a[2]), "r"(a[3]), "r"(b[0]), "r"(b[1]));
}
__device__ __forceinline__ void cp16(uint32_t saddr, const void* gaddr) {
    asm volatile("cp.async.cg.shared.global [%0], [%1], 16;" :: "r"(saddr), "l"(gaddr));
}
#define CP_COMMIT() asm volatile("cp.async.commit_group;" ::: "memory")
#define CP_WAIT1()  asm volatile("cp.async.wait_group 1;" ::: "memory")

// ---------------------------------------------------------------------------
// Fused prep: blocks [0, RP_BLOCKS) build row_ptr (lower_bound on sorted row);
// blocks [RP_BLOCKS, ...) convert W fp32 -> fp16.
// ---------------------------------------------------------------------------
#define RP_BLOCKS ((N_NODES + 1 + 255) / 256)          // 391
#define WC_BLOCKS ((IN_F * OUT_F + 255) / 256)         // 512

__global__ void prep_kernel(const int* __restrict__ row, const float* __restrict__ W)
{
    if (blockIdx.x < RP_BLOCKS) {
        int i = blockIdx.x * blockDim.x + threadIdx.x;
        if (i > N_NODES) return;
        int lo = 0, hi = N_EDGES;
        while (lo < hi) {
            int mid = (lo + hi) >> 1;
            if (row[mid] < i) lo = mid + 1; else hi = mid;
        }
        g_row_ptr[i] = lo;
    } else {
        int i = (blockIdx.x - RP_BLOCKS) * blockDim.x + threadIdx.x;
        if (i >= IN_F * OUT_F) return;
        g_Wh[i] = __float2half_rn(W[i]);
    }
}

// ---------------------------------------------------------------------------
// GEMM + tanh: H[M,256] = tanh(A[M,512] @ W), 1-term fp16 (fp32 accum).
// BM=128, BN=256 (full), BK=64 (8 chunks — halves barrier/loop overhead vs
// BK=32). 512 threads, 16 warps (4m x 4n), warp tile 32x64, 4 k-steps/chunk.
// A: single reg buffer (store-then-reload; one full MMA chunk covers the LDG
// latency) + 2 smem stages. B: 3-stage cp.async ring -> no trailing barrier
// (fast warp at ck+1 writes A stage (ck+1)&1 and B stage (ck+2)%3, disjoint
// from a lagging warp's MMA(ck) reads of stages ck&1 / ck%3).
// Accumulation order identical to the BK=32 version (same 32 k-step sequence).
// ---------------------------------------------------------------------------
#define BKC    64
#define A_PADH 72                           // 144 B row stride (LDSM-safe)
#define B_PADH 264                          // 528 B row stride (LDSM-safe)
#define SZ_A   (128 * A_PADH * 2)           // 18432 B per stage
#define SZ_B   (BKC * B_PADH * 2)           // 33792 B per stage
#define OFF_A(st)   ((st) * SZ_A)
#define OFF_BH(st)  (2 * SZ_A + (st) * SZ_B)
#define GEMM_SMEM   (2 * SZ_A + 3 * SZ_B)   // 138240 B

__global__ __launch_bounds__(512, 1) void gemm_tanh_kernel(
    const float* __restrict__ A, __half* __restrict__ H)
{
    extern __shared__ char smem[];
    const uint32_t sb = smem_u32(smem);
    const int tid  = threadIdx.x;
    const int wid  = tid >> 5, lane = tid & 31;
    const int mwarp = wid & 3, nwarp = wid >> 2;
    const int m0 = blockIdx.x * 128;

    // A load mapping: thread -> row tid/4 (0..127), 16 floats at (tid&3)*16
    const int arow = tid >> 2;
    const int acol = (tid & 3) * 16;
    const bool avalid = (m0 + arow) < N_NODES;
    const float* abase = A + (size_t)(m0 + arow) * IN_F + acol;
    const uint32_t aStsOff = (uint32_t)(arow * A_PADH + acol) * 2;

    // B copy mapping: thread -> k-row tid/8 (0..63), 32 halves at (tid&7)*32
    const int brow = tid >> 3;
    const int bcol = (tid & 7) * 32;
    const size_t  bsrc0 = (size_t)brow * OUT_F + bcol;
    const uint32_t bSts = sb + (uint32_t)(brow * B_PADH + bcol) * 2;

    // ldmatrix lane addressing
    const int q = lane >> 3, rr = lane & 7;
    uint32_t aOff[2];
    #pragma unroll
    for (int mt = 0; mt < 2; mt++) {
        int row  = mwarp * 32 + mt * 16 + (q & 1) * 8 + rr;
        int col8 = (q >> 1) * 8;
        aOff[mt] = (uint32_t)(row * A_PADH + col8) * 2;
    }
    const uint32_t bOff = (uint32_t)((((q & 1) * 8 + rr) * B_PADH) + nwarp * 64 + (q >> 1) * 8) * 2;

    float acc[2][8][4];
    #pragma unroll
    for (int i = 0; i < 2; i++)
        #pragma unroll
        for (int j = 0; j < 8; j++)
            #pragma unroll
            for (int l = 0; l < 4; l++) acc[i][j][l] = 0.0f;

    // prologue: A chunk 0 -> regs; B chunk 0 -> smem stage 0
    float4 pa[4];
    if (avalid) {
        pa[0] = __ldg((const float4*)(abase + 0));
        pa[1] = __ldg((const float4*)(abase + 4));
        pa[2] = __ldg((const float4*)(abase + 8));
        pa[3] = __ldg((const float4*)(abase + 12));
    } else {
        pa[0] = pa[1] = pa[2] = pa[3] = make_float4(0.f, 0.f, 0.f, 0.f);
    }
    {
        const __half* sh = g_Wh + bsrc0;
        cp16(OFF_BH(0) + bSts,      sh);
        cp16(OFF_BH(0) + bSts + 16, sh + 8);
        cp16(OFF_BH(0) + bSts + 32, sh + 16);
        cp16(OFF_BH(0) + bSts + 48, sh + 24);
    }
    CP_COMMIT();

    #pragma unroll
    for (int ck = 0; ck < 8; ck++) {
        const int stA = ck & 1;
        const int stB = ck % 3;
        // prefetch next B into ring stage (ck+1)%3
        if (ck + 1 < 8) {
            const int stBn = (ck + 1) % 3;
            const size_t o = (size_t)(ck + 1) * BKC * OUT_F + bsrc0;
            const __half* sh = g_Wh + o;
            cp16(OFF_BH(stBn) + bSts,      sh);
            cp16(OFF_BH(stBn) + bSts + 16, sh + 8);
            cp16(OFF_BH(stBn) + bSts + 32, sh + 16);
            cp16(OFF_BH(stBn) + bSts + 48, sh + 24);
        }
        CP_COMMIT();

        // convert + store A(ck) fp32 regs -> fp16 smem stage stA
        {
            const float* f = (const float*)pa;
            uint4 u0, u1;
            __half2 h;
            h = __floats2half2_rn(f[0],  f[1]);  u0.x = *(uint32_t*)&h;
            h = __floats2half2_rn(f[2],  f[3]);  u0.y = *(uint32_t*)&h;
            h = __floats2half2_rn(f[4],  f[5]);  u0.z = *(uint32_t*)&h;
            h = __floats2half2_rn(f[6],  f[7]);  u0.w = *(uint32_t*)&h;
            h = __floats2half2_rn(f[8],  f[9]);  u1.x = *(uint32_t*)&h;
            h = __floats2half2_rn(f[10], f[11]); u1.y = *(uint32_t*)&h;
            h = __floats2half2_rn(f[12], f[13]); u1.z = *(uint32_t*)&h;
            h = __floats2half2_rn(f[14], f[15]); u1.w = *(uint32_t*)&h;
            *(uint4*)(smem + OFF_A(stA) + aStsOff)      = u0;
            *(uint4*)(smem + OFF_A(stA) + aStsOff + 16) = u1;
        }
        // reload pa with next chunk (MMA below covers the latency)
        if (ck + 1 < 8) {
            if (avalid) {
                const float* ab = abase + (ck + 1) * BKC;
                pa[0] = __ldg((const float4*)(ab + 0));
                pa[1] = __ldg((const float4*)(ab + 4));
                pa[2] = __ldg((const float4*)(ab + 8));
                pa[3] = __ldg((const float4*)(ab + 12));
            }
        }
        CP_WAIT1();          // B(ck) arrived
        __syncthreads();

        // ---- MMA over stages (stA, stB): 4 k-steps ----
        const uint32_t sa  = sb + OFF_A(stA);
        const uint32_t sbh = sb + OFF_BH(stB);
        #pragma unroll
        for (int s = 0; s < 4; s++) {
            uint32_t a[2][4];
            ldsm_x4(a[0], sa + aOff[0] + s * 32);
            ldsm_x4(a[1], sa + aOff[1] + s * 32);
            #pragma unroll
            for (int np = 0; np < 4; np++) {
                uint32_t bh[4];
                uint32_t ba = bOff + (uint32_t)(s * 16 * B_PADH + np * 16) * 2;
                ldsm_x4_t(bh, sbh + ba);
                #pragma unroll
                for (int mt = 0; mt < 2; mt++) {
                    mma_f16(acc[mt][2*np+0], a[mt], bh + 0);
                    mma_f16(acc[mt][2*np+1], a[mt], bh + 2);
                }
            }
        }
        // no trailing __syncthreads (3-stage B ring + 2-stage A, skew-1 safe)
    }

    // ---- Epilogue: tanh.approx + fp16 store ----
    const int gid = lane >> 2, tig = lane & 3;
    #pragma unroll
    for (int mt = 0; mt < 2; mt++) {
        int row = m0 + mwarp * 32 + mt * 16 + gid;
        #pragma unroll
        for (int nt = 0; nt < 8; nt++) {
            int col = nwarp * 64 + nt * 8 + tig * 2;
            if (row < N_NODES) {
                __half2 v = __floats2half2_rn(tanh_fast(acc[mt][nt][0]), tanh_fast(acc[mt][nt][1]));
                *(__half2*)&H[(size_t)row * OUT_F + col] = v;
            }
            if (row + 8 < N_NODES) {
                __half2 v = __floats2half2_rn(tanh_fast(acc[mt][nt][2]), tanh_fast(acc[mt][nt][3]));
                *(__half2*)&H[(size_t)(row + 8) * OUT_F + col] = v;
            }
        }
    }
}

// ---------------------------------------------------------------------------
// SpMM: one warp per destination row, lane owns 8 halves, fp32 accumulate.
// 2-edge unroll, both gathers issued before either FMA block (round-10/14
// verified config — LTS-bound, so this is at its floor).
// ---------------------------------------------------------------------------
__device__ __forceinline__ void spmm_fma8(float v, const uint4& x, float* acc)
{
    const __half2* hx = (const __half2*)&x;
    #pragma unroll
    for (int j = 0; j < 4; j++) {
        float2 f = __half22float2(hx[j]);
        acc[2*j+0] = fmaf(v, f.x, acc[2*j+0]);
        acc[2*j+1] = fmaf(v, f.y, acc[2*j+1]);
    }
}

__device__ __forceinline__ void spmm_accum(
    int start, int end, int lane,
    const int* __restrict__ col, const float* __restrict__ vals,
    const __half* __restrict__ X, float* acc)
{
    int e = start;
    for (; e + 2 <= end; e += 2) {
        int   c0 = __ldcs(&col[e]);
        int   c1 = __ldcs(&col[e + 1]);
        float v0 = __ldcs(&vals[e]);
        float v1 = __ldcs(&vals[e + 1]);
        uint4 x0 = __ldg((const uint4*)&X[(size_t)c0 * OUT_F + lane * 8]);
        uint4 x1 = __ldg((const uint4*)&X[(size_t)c1 * OUT_F + lane * 8]);
        spmm_fma8(v0, x0, acc);
        spmm_fma8(v1, x1, acc);
    }
    if (e < end) {
        int   c0 = __ldcs(&col[e]);
        float v0 = __ldcs(&vals[e]);
        uint4 x0 = __ldg((const uint4*)&X[(size_t)c0 * OUT_F + lane * 8]);
        spmm_fma8(v0, x0, acc);
    }
}

__global__ __launch_bounds__(256) void spmm_h2h_kernel(
    const int* __restrict__ col, const float* __restrict__ vals,
    const __half* __restrict__ X, __half* __restrict__ Y)
{
    int warp = (blockIdx.x * blockDim.x + threadIdx.x) >> 5;
    int lane = threadIdx.x & 31;
    if (warp >= N_NODES) return;
    float acc[8] = {0,0,0,0,0,0,0,0};
    spmm_accum(g_row_ptr[warp], g_row_ptr[warp + 1], lane, col, vals, X, acc);
    __half2 h0 = __floats2half2_rn(acc[0], acc[1]);
    __half2 h1 = __floats2half2_rn(acc[2], acc[3]);
    __half2 h2 = __floats2half2_rn(acc[4], acc[5]);
    __half2 h3 = __floats2half2_rn(acc[6], acc[7]);
    uint4 u;
    u.x = *(uint32_t*)&h0; u.y = *(uint32_t*)&h1;
    u.z = *(uint32_t*)&h2; u.w = *(uint32_t*)&h3;
    __stcs((uint4*)&Y[(size_t)warp * OUT_F + lane * 8], u);
}

__global__ __launch_bounds__(256) void spmm_h2f_kernel(
    const int* __restrict__ col, const float* __restrict__ vals,
    const __half* __restrict__ X, float* __restrict__ Y)
{
    int warp = (blockIdx.x * blockDim.x + threadIdx.x) >> 5;
    int lane = threadIdx.x & 31;
    if (warp >= N_NODES) return;
    float acc[8] = {0,0,0,0,0,0,0,0};
    spmm_accum(g_row_ptr[warp], g_row_ptr[warp + 1], lane, col, vals, X, acc);
    float* dst = &Y[(size_t)warp * OUT_F + lane * 8];
    __stcs((float4*)&dst[0], make_float4(acc[0], acc[1], acc[2], acc[3]));
    __stcs((float4*)&dst[4], make_float4(acc[4], acc[5], acc[6], acc[7]));
}

// ---------------------------------------------------------------------------
extern "C" void kernel_launch(void* const* d_in, const int* in_sizes, int n_in,
                              void* d_out, int out_size)
{
    const float* features = (const float*)d_in[0];
    const float* weight   = (const float*)d_in[1];
    const int*   row      = (const int*)d_in[2];
    const int*   colv     = (const int*)d_in[3];
    const float* adj      = (const float*)d_in[4];
    float*       out      = (float*)d_out;

    __half* H = nullptr;
    __half* T = nullptr;
    cudaGetSymbolAddress((void**)&H, g_H);
    cudaGetSymbolAddress((void**)&T, g_T);

    cudaFuncSetAttribute(gemm_tanh_kernel,
                         cudaFuncAttributeMaxDynamicSharedMemorySize, GEMM_SMEM);

    // 0. Fused prep: row_ptr + W fp16 conversion (one launch)
    prep_kernel<<<RP_BLOCKS + WC_BLOCKS, 256>>>(row, weight);

    // 1. H = tanh(X @ W), fp16 output (BK=64)
    gemm_tanh_kernel<<<(N_NODES + 127) / 128, 512, GEMM_SMEM>>>(features, H);

    // 2. T = A @ H   (fp16 -> fp16)
    int spmm_blocks = (N_NODES * 32 + 255) / 256;
    spmm_h2h_kernel<<<spmm_blocks, 256>>>(colv, adj, H, T);

    // 3. out = A @ T (fp16 -> fp32)
    spmm_h2f_kernel<<<spmm_blocks, 256>>>(colv, adj, T, out);
}

// round 17
// speedup vs baseline: 1.1406x; 1.1406x over previous
#include <cuda_runtime.h>
#include <cuda_fp16.h>
#include <cstdint>

#define N_NODES 100000
#define N_EDGES 1600000
#define IN_F    512
#define OUT_F   256

// Scratch (no cudaMalloc). H and T are fp16 (range-safe: |H|<=1, |T|<~16).
__device__ __half g_H[(size_t)N_NODES * OUT_F];
__device__ __half g_T[(size_t)N_NODES * OUT_F];
__device__ int    g_row_ptr[N_NODES + 1];
// fp16 weight [512][256], 256 KB — L2-resident.
__device__ __half g_Wh[(size_t)IN_F * OUT_F];

// ---------------------------------------------------------------------------
// helpers
// ---------------------------------------------------------------------------
__device__ __forceinline__ uint32_t smem_u32(const void* p) {
    uint32_t a;
    asm("{ .reg .u64 t; cvta.to.shared.u64 t, %1; cvt.u32.u64 %0, t; }" : "=r"(a) : "l"(p));
    return a;
}
__device__ __forceinline__ float tanh_fast(float x) {
    float y;
    asm("tanh.approx.f32 %0, %1;" : "=f"(y) : "f"(x));
    return y;
}
__device__ __forceinline__ void ldsm_x4(uint32_t* r, uint32_t addr) {
    asm volatile("ldmatrix.sync.aligned.m8n8.x4.shared.b16 {%0,%1,%2,%3}, [%4];"
                 : "=r"(r[0]), "=r"(r[1]), "=r"(r[2]), "=r"(r[3]) : "r"(addr));
}
__device__ __forceinline__ void ldsm_x4_t(uint32_t* r, uint32_t addr) {
    asm volatile("ldmatrix.sync.aligned.m8n8.x4.trans.shared.b16 {%0,%1,%2,%3}, [%4];"
                 : "=r"(r[0]), "=r"(r[1]), "=r"(r[2]), "=r"(r[3]) : "r"(addr));
}
__device__ __forceinline__ void mma_f16(float* c, const uint32_t* a, const uint32_t* b) {
    asm volatile(
        "mma.sync.aligned.m16n8k16.row.col.f32.f16.f16.f32 "
        "{%0,%1,%2,%3}, {%4,%5,%6,%7}, {%8,%9}, {%0,%1,%2,%3};"
        : "+f"(c[0]), "+f"(c[1]), "+f"(c[2]), "+f"(c[3])
        : "r"(a[0]), "r"(a[1]), "r"(a[2]), "r"(a[3]), "r"(b[0]), "r"(b[1]));
}
__device__ __forceinline__ void cp16(uint32_t saddr, const void* gaddr) {
    asm volatile("cp.async.cg.shared.global [%0], [%1], 16;" :: "r"(saddr), "l"(gaddr));
}
#define CP_COMMIT() asm volatile("cp.async.commit_group;" ::: "memory")
#define CP_WAIT1()  asm volatile("cp.async.wait_group 1;" ::: "memory")

// ---------------------------------------------------------------------------
// W fp32 -> fp16 conversion (must precede the GEMM, which reads g_Wh)
// ---------------------------------------------------------------------------
__global__ void wconv_kernel(const float* __restrict__ W)
{
    int i = blockIdx.x * blockDim.x + threadIdx.x;
    if (i >= IN_F * OUT_F) return;
    g_Wh[i] = __float2half_rn(W[i]);
}

// ---------------------------------------------------------------------------
// GEMM + tanh: H[M,256] = tanh(A[M,512] @ W), 1-term fp16 (fp32 accum).
// BM=128, BN=256 (full), BK=32 (16 chunks). 512 threads, 16 warps (4m x 4n).
// A double-buffered in regs+smem; B in 3-stage cp.async ring (no trailing
// barrier — skew-1 safe). Round-14 verified configuration.
//
// Grid fusion: blocks [GEMM_BLOCKS, GEMM_BLOCKS+RP_BLOCKS) build row_ptr
// (lower_bound on sorted `row`). They are appended LAST so they execute in
// the GEMM's underfull tail wave (106 idle SMs) — their cost is hidden.
// GEMM never reads g_row_ptr, so no ordering hazard; the SpMM launches that
// consume g_row_ptr come after this kernel completes.
// ---------------------------------------------------------------------------
#define GEMM_BLOCKS ((N_NODES + 127) / 128)            // 782
#define RP_BLOCKS   ((N_NODES + 1 + 511) / 512)        // 196

#define A_PADH 40
#define B_PADH 264
#define SZ_A   (128 * A_PADH * 2)          // 10240 B per stage
#define SZ_B   (32 * B_PADH * 2)           // 16896 B per stage
#define OFF_A(st)   ((st) * SZ_A)
#define OFF_BH(st)  (2 * SZ_A + (st) * SZ_B)
#define GEMM_SMEM   (2 * SZ_A + 3 * SZ_B)  // 71168 B

__global__ __launch_bounds__(512, 1) void gemm_tanh_kernel(
    const float* __restrict__ A, __half* __restrict__ H,
    const int* __restrict__ rowidx)
{
    // ---- appended tail blocks: row_ptr build ----
    if (blockIdx.x >= GEMM_BLOCKS) {
        int i = (blockIdx.x - GEMM_BLOCKS) * 512 + threadIdx.x;
        if (i <= N_NODES) {
            int lo = 0, hi = N_EDGES;
            while (lo < hi) {
                int mid = (lo + hi) >> 1;
                if (rowidx[mid] < i) lo = mid + 1; else hi = mid;
            }
            g_row_ptr[i] = lo;
        }
        return;
    }

    extern __shared__ char smem[];
    const uint32_t sb = smem_u32(smem);
    const int tid  = threadIdx.x;
    const int wid  = tid >> 5, lane = tid & 31;
    const int mwarp = wid & 3, nwarp = wid >> 2;
    const int m0 = blockIdx.x * 128;

    const int arow = tid >> 2;
    const int acol = (tid & 3) * 8;
    const bool avalid = (m0 + arow) < N_NODES;
    const float* abase = A + (size_t)(m0 + arow) * IN_F + acol;

    const int brow = tid >> 4;
    const int bseg = (tid & 15) * 2;
    const size_t  bsrc0 = (size_t)brow * OUT_F + bseg * 8;
    const uint32_t bSts = sb + (uint32_t)(brow * B_PADH + bseg * 8) * 2;

    const int q = lane >> 3, rr = lane & 7;
    uint32_t aOff[2];
    #pragma unroll
    for (int mt = 0; mt < 2; mt++) {
        int row  = mwarp * 32 + mt * 16 + (q & 1) * 8 + rr;
        int col8 = (q >> 1) * 8;
        aOff[mt] = (uint32_t)(row * A_PADH + col8) * 2;
    }
    const uint32_t bOff = (uint32_t)((((q & 1) * 8 + rr) * B_PADH) + nwarp * 64 + (q >> 1) * 8) * 2;

    float acc[2][8][4];
    #pragma unroll
    for (int i = 0; i < 2; i++)
        #pragma unroll
        for (int j = 0; j < 8; j++)
            #pragma unroll
            for (int l = 0; l < 4; l++) acc[i][j][l] = 0.0f;

    float4 pa[2][2];
    if (avalid) {
        pa[0][0] = __ldg((const float4*)(abase + 0));
        pa[0][1] = __ldg((const float4*)(abase + 4));
    } else {
        pa[0][0] = pa[0][1] = make_float4(0.f, 0.f, 0.f, 0.f);
    }
    {
        const __half* sh = g_Wh + bsrc0;
        cp16(OFF_BH(0) + bSts,      sh);
        cp16(OFF_BH(0) + bSts + 16, sh + 8);
    }
    CP_COMMIT();

    #pragma unroll
    for (int ck = 0; ck < 16; ck++) {
        const int stA = ck & 1;
        const int stB = ck % 3;
        if (ck + 1 < 16) {
            const int stBn = (ck + 1) % 3;
            const size_t o = (size_t)(ck + 1) * 32 * OUT_F + bsrc0;
            const __half* sh = g_Wh + o;
            cp16(OFF_BH(stBn) + bSts,      sh);
            cp16(OFF_BH(stBn) + bSts + 16, sh + 8);
        }
        CP_COMMIT();

        {
            __half2 h0 = __floats2half2_rn(pa[stA][0].x, pa[stA][0].y);
            __half2 h1 = __floats2half2_rn(pa[stA][0].z, pa[stA][0].w);
            __half2 h2 = __floats2half2_rn(pa[stA][1].x, pa[stA][1].y);
            __half2 h3 = __floats2half2_rn(pa[stA][1].z, pa[stA][1].w);
            uint4 u;
            u.x = *(uint32_t*)&h0; u.y = *(uint32_t*)&h1;
            u.z = *(uint32_t*)&h2; u.w = *(uint32_t*)&h3;
            *(uint4*)(smem + OFF_A(stA) + (uint32_t)(arow * A_PADH + acol) * 2) = u;
        }
        if (ck + 1 < 16) {
            if (avalid) {
                pa[stA ^ 1][0] = __ldg((const float4*)(abase + (ck + 1) * 32));
                pa[stA ^ 1][1] = __ldg((const float4*)(abase + (ck + 1) * 32 + 4));
            }
        }
        CP_WAIT1();
        __syncthreads();

        const uint32_t sa  = sb + OFF_A(stA);
        const uint32_t sbh = sb + OFF_BH(stB);
        #pragma unroll
        for (int s = 0; s < 2; s++) {
            uint32_t a[2][4];
            ldsm_x4(a[0], sa + aOff[0] + s * 32);
            ldsm_x4(a[1], sa + aOff[1] + s * 32);
            #pragma unroll
            for (int np = 0; np < 4; np++) {
                uint32_t bh[4];
                uint32_t ba = bOff + (uint32_t)(s * 16 * B_PADH + np * 16) * 2;
                ldsm_x4_t(bh, sbh + ba);
                #pragma unroll
                for (int mt = 0; mt < 2; mt++) {
                    mma_f16(acc[mt][2*np+0], a[mt], bh + 0);
                    mma_f16(acc[mt][2*np+1], a[mt], bh + 2);
                }
            }
        }
        // no trailing __syncthreads (3-stage B ring + 2-stage A, skew-1 safe)
    }

    const int gid = lane >> 2, tig = lane & 3;
    #pragma unroll
    for (int mt = 0; mt < 2; mt++) {
        int row = m0 + mwarp * 32 + mt * 16 + gid;
        #pragma unroll
        for (int nt = 0; nt < 8; nt++) {
            int col = nwarp * 64 + nt * 8 + tig * 2;
            if (row < N_NODES) {
                __half2 v = __floats2half2_rn(tanh_fast(acc[mt][nt][0]), tanh_fast(acc[mt][nt][1]));
                *(__half2*)&H[(size_t)row * OUT_F + col] = v;
            }
            if (row + 8 < N_NODES) {
                __half2 v = __floats2half2_rn(tanh_fast(acc[mt][nt][2]), tanh_fast(acc[mt][nt][3]));
                *(__half2*)&H[(size_t)(row + 8) * OUT_F + col] = v;
            }
        }
    }
}

// ---------------------------------------------------------------------------
// SpMM: one warp per destination row, lane owns 8 halves, fp32 accumulate.
// 2-edge unroll, both gathers issued before either FMA block.
// (LTS-throughput-bound at ~6300 B/cyc — verified at its floor.)
// ---------------------------------------------------------------------------
__device__ __forceinline__ void spmm_fma8(float v, const uint4& x, float* acc)
{
    const __half2* hx = (const __half2*)&x;
    #pragma unroll
    for (int j = 0; j < 4; j++) {
        float2 f = __half22float2(hx[j]);
        acc[2*j+0] = fmaf(v, f.x, acc[2*j+0]);
        acc[2*j+1] = fmaf(v, f.y, acc[2*j+1]);
    }
}

__device__ __forceinline__ void spmm_accum(
    int start, int end, int lane,
    const int* __restrict__ col, const float* __restrict__ vals,
    const __half* __restrict__ X, float* acc)
{
    int e = start;
    for (; e + 2 <= end; e += 2) {
        int   c0 = __ldcs(&col[e]);
        int   c1 = __ldcs(&col[e + 1]);
        float v0 = __ldcs(&vals[e]);
        float v1 = __ldcs(&vals[e + 1]);
        uint4 x0 = __ldg((const uint4*)&X[(size_t)c0 * OUT_F + lane * 8]);
        uint4 x1 = __ldg((const uint4*)&X[(size_t)c1 * OUT_F + lane * 8]);
        spmm_fma8(v0, x0, acc);
        spmm_fma8(v1, x1, acc);
    }
    if (e < end) {
        int   c0 = __ldcs(&col[e]);
        float v0 = __ldcs(&vals[e]);
        uint4 x0 = __ldg((const uint4*)&X[(size_t)c0 * OUT_F + lane * 8]);
        spmm_fma8(v0, x0, acc);
    }
}

__global__ __launch_bounds__(256) void spmm_h2h_kernel(
    const int* __restrict__ col, const float* __restrict__ vals,
    const __half* __restrict__ X, __half* __restrict__ Y)
{
    int warp = (blockIdx.x * blockDim.x + threadIdx.x) >> 5;
    int lane = threadIdx.x & 31;
    if (warp >= N_NODES) return;
    float acc[8] = {0,0,0,0,0,0,0,0};
    spmm_accum(g_row_ptr[warp], g_row_ptr[warp + 1], lane, col, vals, X, acc);
    __half2 h0 = __floats2half2_rn(acc[0], acc[1]);
    __half2 h1 = __floats2half2_rn(acc[2], acc[3]);
    __half2 h2 = __floats2half2_rn(acc[4], acc[5]);
    __half2 h3 = __floats2half2_rn(acc[6], acc[7]);
    uint4 u;
    u.x = *(uint32_t*)&h0; u.y = *(uint32_t*)&h1;
    u.z = *(uint32_t*)&h2; u.w = *(uint32_t*)&h3;
    __stcs((uint4*)&Y[(size_t)warp * OUT_F + lane * 8], u);
}

__global__ __launch_bounds__(256) void spmm_h2f_kernel(
    const int* __restrict__ col, const float* __restrict__ vals,
    const __half* __restrict__ X, float* __restrict__ Y)
{
    int warp = (blockIdx.x * blockDim.x + threadIdx.x) >> 5;
    int lane = threadIdx.x & 31;
    if (warp >= N_NODES) return;
    float acc[8] = {0,0,0,0,0,0,0,0};
    spmm_accum(g_row_ptr[warp], g_row_ptr[warp + 1], lane, col, vals, X, acc);
    float* dst = &Y[(size_t)warp * OUT_F + lane * 8];
    __stcs((float4*)&dst[0], make_float4(acc[0], acc[1], acc[2], acc[3]));
    __stcs((float4*)&dst[4], make_float4(acc[4], acc[5], acc[6], acc[7]));
}

// ---------------------------------------------------------------------------
extern "C" void kernel_launch(void* const* d_in, const int* in_sizes, int n_in,
                              void* d_out, int out_size)
{
    const float* features = (const float*)d_in[0];
    const float* weight   = (const float*)d_in[1];
    const int*   row      = (const int*)d_in[2];
    const int*   colv     = (const int*)d_in[3];
    const float* adj      = (const float*)d_in[4];
    float*       out      = (float*)d_out;

    __half* H = nullptr;
    __half* T = nullptr;
    cudaGetSymbolAddress((void**)&H, g_H);
    cudaGetSymbolAddress((void**)&T, g_T);

    cudaFuncSetAttribute(gemm_tanh_kernel,
                         cudaFuncAttributeMaxDynamicSharedMemorySize, GEMM_SMEM);

    // 0. W -> fp16 (GEMM depends on this)
    wconv_kernel<<<(IN_F * OUT_F + 255) / 256, 256>>>(weight);

    // 1. H = tanh(X @ W); row_ptr blocks appended, hidden in the tail wave
    gemm_tanh_kernel<<<GEMM_BLOCKS + RP_BLOCKS, 512, GEMM_SMEM>>>(features, H, row);

    // 2. T = A @ H   (fp16 -> fp16)
    int spmm_blocks = (N_NODES * 32 + 255) / 256;
    spmm_h2h_kernel<<<spmm_blocks, 256>>>(colv, adj, H, T);

    // 3. out = A @ T (fp16 -> fp32)
    spmm_h2f_kernel<<<spmm_blocks, 256>>>(colv, adj, T, out);
}